// round 15
// baseline (speedup 1.0000x reference)
#include <cuda_runtime.h>
#include <math.h>
#include <stdint.h>

// Problem constants
#define B_  4
#define C_  128
#define H_B 512
#define W_B 512
#define H_C 64
#define W_C 2048
#define BC_ (B_ * C_)            // 512 planes
#define ROW_BYTES (W_C * 4)      // 8192 bytes: one full output row

__device__ __forceinline__ uint32_t smem_u32(const void* p) {
    uint32_t a;
    asm("{ .reg .u64 t; cvta.to.shared.u64 t, %1; cvt.u32.u64 %0, t; }"
        : "=r"(a) : "l"(p));
    return a;
}

// One CTA per bc plane.  512 threads.
// Phase A: gather all 2048 column values (4 per thread) into 8 KB SMEM.
// Phase B: threads 0..63 EACH issue one 8 KB cp.async.bulk copy of the same
// SMEM row to output row t -> per-CTA writes form one contiguous sequential
// 512 KB burst (DRAM row-buffer locality) while issue stays parallel
// (~224 issuing threads per SM), fixing R12's serial-issue collapse.
__global__ __launch_bounds__(512) void bev2cyl_rowp(const float* __restrict__ bev,
                                                    float* __restrict__ out) {
    __shared__ __align__(128) float s_col[W_C];

    const int t  = threadIdx.x;
    const int bc = blockIdx.x;

    const float* __restrict__ plane = bev + (size_t)bc * (H_B * W_B);

    // ---- Phase A: four columns per thread ----
    const float STEP = (float)(6.283185307179586 / 2047.0);
#pragma unroll
    for (int k = 0; k < 4; k++) {
        int w = k * 512 + t;                      // 0..2047

        float phi = fmaf((float)w, STEP, -3.14159265358979f);
        float s, c;
        sincosf(phi, &s, &c);
        float x = (50.0f * c + 50.0f) * (511.0f / 100.0f);
        float y = (50.0f - 50.0f * s) * (511.0f / 100.0f);

        float fx0 = floorf(x), fy0 = floorf(y);
        int x0 = (int)fx0, y0 = (int)fy0;
        int x1 = x0 + 1,  y1 = y0 + 1;
        float wx1 = x - fx0, wx0 = 1.0f - wx1;
        float wy1 = y - fy0, wy0 = 1.0f - wy1;

        bool vx0 = (x0 >= 0) && (x0 < W_B);
        bool vx1 = (x1 >= 0) && (x1 < W_B);
        bool vy0 = (y0 >= 0) && (y0 < H_B);
        bool vy1 = (y1 >= 0) && (y1 < H_B);

        int x0c = min(max(x0, 0), W_B - 1);
        int x1c = min(max(x1, 0), W_B - 1);
        int y0c = min(max(y0, 0), H_B - 1);
        int y1c = min(max(y1, 0), H_B - 1);

        float w00 = (vx0 && vy0) ? wx0 * wy0 : 0.0f;
        float w10 = (vx1 && vy0) ? wx1 * wy0 : 0.0f;
        float w01 = (vx0 && vy1) ? wx0 * wy1 : 0.0f;
        float w11 = (vx1 && vy1) ? wx1 * wy1 : 0.0f;

        float p00 = __ldg(plane + y0c * W_B + x0c);
        float p10 = __ldg(plane + y0c * W_B + x1c);
        float p01 = __ldg(plane + y1c * W_B + x0c);
        float p11 = __ldg(plane + y1c * W_B + x1c);

        s_col[w] = p00 * w00 + p10 * w10 + p01 * w01 + p11 * w11;
    }
    __syncthreads();

    // ---- Phase B: 64 parallel 8 KB bulk copies, one per thread ----
    if (t < H_C) {
        asm volatile("fence.proxy.async.shared::cta;" ::: "memory");
        uint32_t saddr = smem_u32(s_col);
        // out[bc] block is contiguous 512 KB; row t at offset t*8KB
        float* dst = out + (size_t)bc * (H_C * W_C) + (size_t)t * W_C;
        asm volatile(
            "cp.async.bulk.global.shared::cta.bulk_group [%0], [%1], %2;"
            :: "l"(dst), "r"(saddr), "n"(ROW_BYTES) : "memory");
        asm volatile("cp.async.bulk.commit_group;" ::: "memory");
        asm volatile("cp.async.bulk.wait_group 0;" ::: "memory");
    }
}

extern "C" void kernel_launch(void* const* d_in, const int* in_sizes, int n_in,
                              void* d_out, int out_size) {
    const float* bev = (const float*)d_in[0];
    float* out = (float*)d_out;

    bev2cyl_rowp<<<BC_, 512>>>(bev, out);   // 512 CTAs, one per (b,c) plane
}

// round 17
// speedup vs baseline: 1.0741x; 1.0741x over previous
#include <cuda_runtime.h>
#include <math.h>
#include <stdint.h>

// Problem constants
#define B_  4
#define C_  128
#define H_B 512
#define W_B 512
#define H_C 64
#define W_C 2048
#define BC_ (B_ * C_)          // 512 planes

#define WCH 512                // w columns per CTA
#define NCHUNK (W_C / WCH)     // 4 chunks per plane -> 2048 CTAs
#define CHUNK_BYTES (WCH * 4)  // 2048 bytes

__device__ __forceinline__ uint32_t smem_u32(const void* p) {
    uint32_t a;
    asm("{ .reg .u64 t; cvta.to.shared.u64 t, %1; cvt.u32.u64 %0, t; }"
        : "=r"(a) : "l"(p));
    return a;
}

// One CTA per (bc, 512-wide w chunk).  256 threads.  Hybrid store paths:
//   rows  0..31 -> TMA bulk copies (8 warps x 4, lane 0 issues)
//   rows 32..63 -> per-thread STG.128 evict-first stores (all 256 threads)
// Both paths run concurrently, doubling the write-supply machinery feeding
// the (measured 31%-idle) DRAM write queues.
__global__ __launch_bounds__(256) void bev2cyl_hybrid(const float* __restrict__ bev,
                                                      float* __restrict__ out) {
    __shared__ __align__(128) float s_col[WCH];

    const int t     = threadIdx.x;
    const int bc    = blockIdx.x >> 2;            // / NCHUNK
    const int chunk = blockIdx.x & (NCHUNK - 1);
    const int wbase = chunk * WCH;

    const float* __restrict__ plane = bev + (size_t)bc * (H_B * W_B);

    // ---- Phase A: gather two columns per thread ----
    const float STEP = (float)(6.283185307179586 / 2047.0);
#pragma unroll
    for (int k = 0; k < 2; k++) {
        int wi = k * 256 + t;                     // 0..511 within chunk
        int w  = wbase + wi;

        float phi = fmaf((float)w, STEP, -3.14159265358979f);
        float s, c;
        sincosf(phi, &s, &c);
        float x = (50.0f * c + 50.0f) * (511.0f / 100.0f);
        float y = (50.0f - 50.0f * s) * (511.0f / 100.0f);

        float fx0 = floorf(x), fy0 = floorf(y);
        int x0 = (int)fx0, y0 = (int)fy0;
        int x1 = x0 + 1,  y1 = y0 + 1;
        float wx1 = x - fx0, wx0 = 1.0f - wx1;
        float wy1 = y - fy0, wy0 = 1.0f - wy1;

        bool vx0 = (x0 >= 0) && (x0 < W_B);
        bool vx1 = (x1 >= 0) && (x1 < W_B);
        bool vy0 = (y0 >= 0) && (y0 < H_B);
        bool vy1 = (y1 >= 0) && (y1 < H_B);

        int x0c = min(max(x0, 0), W_B - 1);
        int x1c = min(max(x1, 0), W_B - 1);
        int y0c = min(max(y0, 0), H_B - 1);
        int y1c = min(max(y1, 0), H_B - 1);

        float w00 = (vx0 && vy0) ? wx0 * wy0 : 0.0f;
        float w10 = (vx1 && vy0) ? wx1 * wy0 : 0.0f;
        float w01 = (vx0 && vy1) ? wx0 * wy1 : 0.0f;
        float w11 = (vx1 && vy1) ? wx1 * wy1 : 0.0f;

        float p00 = __ldg(plane + y0c * W_B + x0c);
        float p10 = __ldg(plane + y0c * W_B + x1c);
        float p01 = __ldg(plane + y1c * W_B + x0c);
        float p11 = __ldg(plane + y1c * W_B + x1c);

        s_col[wi] = p00 * w00 + p10 * w10 + p01 * w01 + p11 * w11;
    }
    __syncthreads();

    // Base of this CTA's output tile (float index)
    float* dst_base = out + (size_t)bc * (H_C * W_C) + wbase;

    // ---- Phase B1: TMA bulk stores for rows 0..31 (lane 0 of each warp) ----
    const int warp = t >> 5;
    const int lane = t & 31;
    if (lane == 0) {
        asm volatile("fence.proxy.async.shared::cta;" ::: "memory");
        uint32_t saddr = smem_u32(s_col);
#pragma unroll
        for (int i = 0; i < 4; i++) {
            int h = warp * 4 + i;                 // rows 0..31
            float* dst = dst_base + (size_t)h * W_C;
            asm volatile(
                "cp.async.bulk.global.shared::cta.bulk_group [%0], [%1], %2;"
                :: "l"(dst), "r"(saddr), "n"(CHUNK_BYTES) : "memory");
        }
        asm volatile("cp.async.bulk.commit_group;" ::: "memory");
    }

    // ---- Phase B2: concurrent STG path for rows 32..63 (all 256 threads) ----
    {
        const int quad  = t & 127;                // 0..127 float4 across 512 cols
        const int hhalf = t >> 7;                 // 0 or 1
        const float4* __restrict__ s4 = (const float4*)s_col;
        float4 val = s4[quad];

        float4* __restrict__ out4 = (float4*)dst_base;  // quad stride W_C/4=512
        size_t qbase = (size_t)quad;
#pragma unroll 16
        for (int i = 0; i < 16; i++) {
            int h = 32 + hhalf * 16 + i;          // rows 32..63
            __stcs(out4 + qbase + (size_t)h * (W_C / 4), val);
        }
    }

    // ---- Drain TMA group (issuing threads only) ----
    if (lane == 0) {
        asm volatile("cp.async.bulk.wait_group 0;" ::: "memory");
    }
}

extern "C" void kernel_launch(void* const* d_in, const int* in_sizes, int n_in,
                              void* d_out, int out_size) {
    const float* bev = (const float*)d_in[0];
    float* out = (float*)d_out;

    bev2cyl_hybrid<<<BC_ * NCHUNK, 256>>>(bev, out);   // 2048 CTAs
}